// round 11
// baseline (speedup 1.0000x reference)
#include <cuda_runtime.h>

#define NTOK 8192
#define DIM 128
#define ODIM 128
#define THREADS 64
#define OT 4
#define TOKPT 4

typedef unsigned long long u64;

__device__ float g_xnT[DIM * NTOK];   // transposed: [d][n]
__device__ float2 g_musv[NTOK];

__device__ __forceinline__ float2 ffma2(float2 a, float2 b, float2 c) {
    float2 d;
    asm("fma.rn.f32x2 %0, %1, %2, %3;"
        : "=l"(reinterpret_cast<u64&>(d))
        : "l"(reinterpret_cast<u64 const&>(a)),
          "l"(reinterpret_cast<u64 const&>(b)),
          "l"(reinterpret_cast<u64 const&>(c)));
    return d;
}
__device__ __forceinline__ float2 fmul2(float2 a, float2 b) {
    float2 d;
    asm("mul.rn.f32x2 %0, %1, %2;"
        : "=l"(reinterpret_cast<u64&>(d))
        : "l"(reinterpret_cast<u64 const&>(a)),
          "l"(reinterpret_cast<u64 const&>(b)));
    return d;
}
__device__ __forceinline__ float ex2f(float a) {
    float r; asm("ex2.approx.ftz.f32 %0, %1;" : "=f"(r) : "f"(a)); return r;
}
__device__ __forceinline__ float lg2f(float a) {
    float r; asm("lg2.approx.ftz.f32 %0, %1;" : "=f"(r) : "f"(a)); return r;
}

// ---------------- Kernel 1: LayerNorm + transpose (warp per token) ----------------
__global__ void ln_kernel(const float* __restrict__ x,
                          const float* __restrict__ gamma,
                          const float* __restrict__ beta) {
    __shared__ float sX[8][DIM];
    const int tok0 = blockIdx.x * 8;
    const int w = threadIdx.x >> 5;
    const int lane = threadIdx.x & 31;
    const int token = tok0 + w;

    float4 v = ((const float4*)(x + (size_t)token * DIM))[lane];
    float s = (v.x + v.y) + (v.z + v.w);
    #pragma unroll
    for (int off = 16; off; off >>= 1) s += __shfl_xor_sync(~0u, s, off);
    float mu = s * (1.0f / DIM);
    float dx = v.x - mu, dy = v.y - mu, dz = v.z - mu, dw = v.w - mu;
    float q = (dx * dx + dy * dy) + (dz * dz + dw * dw);
    #pragma unroll
    for (int off = 16; off; off >>= 1) q += __shfl_xor_sync(~0u, q, off);
    float ve = q * (1.0f / DIM) + 1e-5f;
    float r = rsqrtf(ve);
    float4 g = ((const float4*)gamma)[lane];
    float4 b = ((const float4*)beta)[lane];
    float4 o;
    o.x = fmaf(dx * r, g.x, b.x);
    o.y = fmaf(dy * r, g.y, b.y);
    o.z = fmaf(dz * r, g.z, b.z);
    o.w = fmaf(dw * r, g.w, b.w);
    ((float4*)&sX[w][0])[lane] = o;
    if (lane == 0) g_musv[token] = make_float2(mu, ve * r);  // (mu, sqrt(var+eps))
    __syncthreads();

    const int d = threadIdx.x >> 1;
    const int h = threadIdx.x & 1;
    float4 val;
    val.x = sX[4 * h + 0][d];
    val.y = sX[4 * h + 1][d];
    val.z = sX[4 * h + 2][d];
    val.w = sX[4 * h + 3][d];
    *((float4*)(g_xnT + (size_t)d * NTOK + tok0 + 4 * h)) = val;
}

// ---------------- Kernel 2: fused wavelet + base, 64-thread CTAs ----------------
// m = a*xn^2 + b*xn + cm ; a=-H/s^2, b=-2at, cm=a t^2 + H, H=1/(2 ln2)
//   wavelet contribution = CP * m * 2^m,  CP = -C*ww/(H*2^H) = -0.7292730*ww
// base in xn-domain: b_o = sv*(acc_o - K1_o) + mu*K2_o
__global__ __launch_bounds__(THREADS, 8)
void wave_kernel(const float* __restrict__ scale,
                 const float* __restrict__ trans,
                 const float* __restrict__ ww,
                 const float* __restrict__ bw,
                 const float* __restrict__ gamma,
                 const float* __restrict__ beta,
                 float* __restrict__ out) {
    __shared__ float4 sA [OT][DIM / 4];
    __shared__ float4 sB [OT][DIM / 4];
    __shared__ float4 sCM[OT][DIM / 4];
    __shared__ float4 sCP[OT][DIM / 4];
    __shared__ float4 sW [OT][DIM / 4];
    __shared__ float  sK1[OT], sK2[OT];

    const int o0 = blockIdx.y * OT;
    const int tid = threadIdx.x;
    const float H = 0.72134752f;

    // ---- fold params (cheap softplus via ex2/lg2) ----
    #pragma unroll
    for (int k = 0; k < (OT * DIM) / THREADS; k++) {
        int i = tid + k * THREADS;              // scalar index < 512
        int gi = o0 * DIM + i;
        int d = i & (DIM - 1);
        float sc = scale[gi];
        float sp = (sc > 20.0f) ? sc
                 : 0.69314718f * lg2f(1.0f + ex2f(1.44269504f * sc));
        float s = sp + 0.1f;
        float a = -H / (s * s);
        float tv = trans[gi];
        ((float*)sA)[i]  = a;
        ((float*)sB)[i]  = -2.0f * a * tv;
        ((float*)sCM)[i] = fmaf(a * tv, tv, H);
        ((float*)sCP)[i] = -0.7292730f * ww[gi];
        ((float*)sW)[i]  = bw[gi] / gamma[d];
    }
    __syncthreads();

    // ---- K1, K2: warp w handles o = 2w, 2w+1 ----
    {
        int w = tid >> 5, lane = tid & 31;
        #pragma unroll
        for (int rep = 0; rep < 2; rep++) {
            int o = 2 * w + rep;
            float4 wp = sW[o][lane];
            float4 g4 = ((const float4*)gamma)[lane];
            float4 b4 = ((const float4*)beta)[lane];
            float k1 = (wp.x * b4.x + wp.y * b4.y) + (wp.z * b4.z + wp.w * b4.w);
            float k2 = (wp.x * g4.x + wp.y * g4.y) + (wp.z * g4.z + wp.w * g4.w);
            #pragma unroll
            for (int off = 16; off; off >>= 1) {
                k1 += __shfl_xor_sync(~0u, k1, off);
                k2 += __shfl_xor_sync(~0u, k2, off);
            }
            if (lane == 0) { sK1[o] = k1; sK2[o] = k2; }
        }
    }
    __syncthreads();

    const int n0 = blockIdx.x * (THREADS * TOKPT) + tid;  // token t at n0 + t*THREADS
    const float* xT = g_xnT + n0;

    float2 accw[OT][TOKPT], accb[OT][TOKPT];
    #pragma unroll
    for (int o = 0; o < OT; o++)
        #pragma unroll
        for (int t = 0; t < TOKPT; t++) {
            accw[o][t] = make_float2(0.0f, 0.0f);
            accb[o][t] = make_float2(0.0f, 0.0f);
        }

    for (int dc = 0; dc < DIM / 4; dc++) {
        const float* p = xT + (size_t)(4 * dc) * NTOK;
        float2 xp[TOKPT][2], xq[TOKPT][2];
        #pragma unroll
        for (int t = 0; t < TOKPT; t++) {
            const float* pt = p + t * THREADS;
            xp[t][0] = make_float2(pt[0],        pt[NTOK]);
            xp[t][1] = make_float2(pt[2 * NTOK], pt[3 * NTOK]);
            xq[t][0] = fmul2(xp[t][0], xp[t][0]);
            xq[t][1] = fmul2(xp[t][1], xp[t][1]);
        }

        #pragma unroll
        for (int o = 0; o < OT; o++) {
            float4 A4 = sA [o][dc];
            float4 B4 = sB [o][dc];
            float4 M4 = sCM[o][dc];
            float4 P4 = sCP[o][dc];
            float4 W4 = sW [o][dc];
            float2 Al = make_float2(A4.x, A4.y), Ah = make_float2(A4.z, A4.w);
            float2 Bl = make_float2(B4.x, B4.y), Bh = make_float2(B4.z, B4.w);
            float2 Ml = make_float2(M4.x, M4.y), Mh = make_float2(M4.z, M4.w);
            float2 Pl = make_float2(P4.x, P4.y), Ph = make_float2(P4.z, P4.w);
            float2 Wl = make_float2(W4.x, W4.y), Wh = make_float2(W4.z, W4.w);
            #pragma unroll
            for (int t = 0; t < TOKPT; t++) {
                {
                    float2 m = ffma2(xq[t][0], Al, ffma2(xp[t][0], Bl, Ml));
                    float2 e = make_float2(ex2f(m.x), ex2f(m.y));
                    float2 g = fmul2(m, e);
                    accw[o][t] = ffma2(g, Pl, accw[o][t]);
                }
                {
                    float2 m = ffma2(xq[t][1], Ah, ffma2(xp[t][1], Bh, Mh));
                    float2 e = make_float2(ex2f(m.x), ex2f(m.y));
                    float2 g = fmul2(m, e);
                    accw[o][t] = ffma2(g, Ph, accw[o][t]);
                }
                accb[o][t] = ffma2(xp[t][0], Wl, accb[o][t]);
                accb[o][t] = ffma2(xp[t][1], Wh, accb[o][t]);
            }
        }
    }

    // ---- epilogue ----
    #pragma unroll
    for (int t = 0; t < TOKPT; t++) {
        int n = n0 + t * THREADS;
        float2 ms = g_musv[n];
        float* op = out + (size_t)n * ODIM + o0;
        float4 res;
        float* rp = (float*)&res;
        #pragma unroll
        for (int j = 0; j < 4; j++) {
            float ac = accb[j][t].x + accb[j][t].y;
            float b = fmaf(ms.y, ac - sK1[j], ms.x * sK2[j]);
            float e = ex2f(-1.44269504f * b);
            float sig = __frcp_rn(1.0f + e);
            rp[j] = fmaf(b, sig, accw[j][t].x + accw[j][t].y);
        }
        ((float4*)op)[0] = res;
    }
}

extern "C" void kernel_launch(void* const* d_in, const int* in_sizes, int n_in,
                              void* d_out, int out_size) {
    const float* x     = (const float*)d_in[0];
    const float* scale = (const float*)d_in[1];
    const float* trans = (const float*)d_in[2];
    const float* ww    = (const float*)d_in[3];
    const float* bw    = (const float*)d_in[4];
    const float* gamma = (const float*)d_in[5];
    const float* beta  = (const float*)d_in[6];
    float* out = (float*)d_out;

    ln_kernel<<<NTOK / 8, 256>>>(x, gamma, beta);
    dim3 grid(NTOK / (THREADS * TOKPT), ODIM / OT);
    wave_kernel<<<grid, THREADS>>>(scale, trans, ww, bw, gamma, beta, out);
}

// round 12
// speedup vs baseline: 1.0451x; 1.0451x over previous
#include <cuda_runtime.h>
#include <cuda_fp16.h>

#define NTOK 8192
#define DIM 128
#define ODIM 128
#define THREADS 256
#define OT 4
#define TOKPT 4

typedef unsigned long long u64;
typedef unsigned int u32;

__device__ float g_xnT[DIM * NTOK];   // transposed: [d][n]
__device__ float2 g_musv[NTOK];

__device__ __forceinline__ float2 ffma2(float2 a, float2 b, float2 c) {
    float2 d;
    asm("fma.rn.f32x2 %0, %1, %2, %3;"
        : "=l"(reinterpret_cast<u64&>(d))
        : "l"(reinterpret_cast<u64 const&>(a)),
          "l"(reinterpret_cast<u64 const&>(b)),
          "l"(reinterpret_cast<u64 const&>(c)));
    return d;
}
__device__ __forceinline__ float2 fmul2(float2 a, float2 b) {
    float2 d;
    asm("mul.rn.f32x2 %0, %1, %2;"
        : "=l"(reinterpret_cast<u64&>(d))
        : "l"(reinterpret_cast<u64 const&>(a)),
          "l"(reinterpret_cast<u64 const&>(b)));
    return d;
}
__device__ __forceinline__ float ex2f(float a) {
    float r; asm("ex2.approx.ftz.f32 %0, %1;" : "=f"(r) : "f"(a)); return r;
}
// pack two f32 -> f16x2 (lo lane = lo arg) : single F2FP, fixed-latency fma/alu pipe
__device__ __forceinline__ u32 pack2(float lo, float hi) {
    u32 r;
    asm("cvt.rn.f16x2.f32 %0, %1, %2;" : "=r"(r) : "f"(hi), "f"(lo));
    return r;
}
__device__ __forceinline__ u32 ex2h2(u32 a) {
    u32 r; asm("ex2.approx.f16x2 %0, %1;" : "=r"(r) : "r"(a)); return r;
}
__device__ __forceinline__ u32 hmul2(u32 a, u32 b) {
    u32 r; asm("mul.rn.f16x2 %0, %1, %2;" : "=r"(r) : "r"(a), "r"(b)); return r;
}
__device__ __forceinline__ u32 hfma2(u32 a, u32 b, u32 c) {
    u32 r; asm("fma.rn.f16x2 %0, %1, %2, %3;" : "=r"(r) : "r"(a), "r"(b), "r"(c));
    return r;
}

// ---------------- Kernel 1: LayerNorm + transpose (warp per token) ----------------
__global__ void ln_kernel(const float* __restrict__ x,
                          const float* __restrict__ gamma,
                          const float* __restrict__ beta) {
    __shared__ float sX[8][DIM];
    const int tok0 = blockIdx.x * 8;
    const int w = threadIdx.x >> 5;
    const int lane = threadIdx.x & 31;
    const int token = tok0 + w;

    float4 v = ((const float4*)(x + (size_t)token * DIM))[lane];
    float s = (v.x + v.y) + (v.z + v.w);
    #pragma unroll
    for (int off = 16; off; off >>= 1) s += __shfl_xor_sync(~0u, s, off);
    float mu = s * (1.0f / DIM);
    float dx = v.x - mu, dy = v.y - mu, dz = v.z - mu, dw = v.w - mu;
    float q = (dx * dx + dy * dy) + (dz * dz + dw * dw);
    #pragma unroll
    for (int off = 16; off; off >>= 1) q += __shfl_xor_sync(~0u, q, off);
    float ve = q * (1.0f / DIM) + 1e-5f;
    float r = rsqrtf(ve);
    float4 g = ((const float4*)gamma)[lane];
    float4 b = ((const float4*)beta)[lane];
    float4 o;
    o.x = fmaf(dx * r, g.x, b.x);
    o.y = fmaf(dy * r, g.y, b.y);
    o.z = fmaf(dz * r, g.z, b.z);
    o.w = fmaf(dw * r, g.w, b.w);
    ((float4*)&sX[w][0])[lane] = o;
    if (lane == 0) g_musv[token] = make_float2(mu, ve * r);
    __syncthreads();

    const int d = threadIdx.x >> 1;
    const int h = threadIdx.x & 1;
    float4 val;
    val.x = sX[4 * h + 0][d];
    val.y = sX[4 * h + 1][d];
    val.z = sX[4 * h + 2][d];
    val.w = sX[4 * h + 3][d];
    *((float4*)(g_xnT + (size_t)d * NTOK + tok0 + 4 * h)) = val;
}

// ---------------- Kernel 2: fused wavelet + base (f16x2 exp path) ----------------
// m = a*xn^2 + b*xn + cm (f32, quadratic form); term = CP * m * 2^m (f16x2)
// base in xn-domain: b_o = sv*(acc_o - K1_o) + mu*K2_o
__global__ __launch_bounds__(THREADS, 2)
void wave_kernel(const float* __restrict__ scale,
                 const float* __restrict__ trans,
                 const float* __restrict__ ww,
                 const float* __restrict__ bw,
                 const float* __restrict__ gamma,
                 const float* __restrict__ beta,
                 float* __restrict__ out) {
    __shared__ float4 sA [OT][DIM / 4];
    __shared__ float4 sB [OT][DIM / 4];
    __shared__ float4 sCM[OT][DIM / 4];
    __shared__ float4 sW [OT][DIM / 4];
    __shared__ uint2  sCPh[OT][DIM / 4];   // CP packed as half2 per d-pair
    __shared__ float  sK1[OT], sK2[OT];

    const int o0 = blockIdx.y * OT;
    const int tid = threadIdx.x;
    const float H = 0.72134752f;

    // ---- fold params ----
    #pragma unroll
    for (int k = 0; k < (OT * DIM) / THREADS; k++) {
        int i = tid + k * THREADS;              // scalar index < 512
        int gi = o0 * DIM + i;
        int d = i & (DIM - 1);
        float sc = scale[gi];
        float sp = (sc > 20.0f) ? sc : log1pf(expf(sc));
        float s = sp + 0.1f;
        float a = -H / (s * s);
        float tv = trans[gi];
        ((float*)sA)[i]  = a;
        ((float*)sB)[i]  = -2.0f * a * tv;
        ((float*)sCM)[i] = fmaf(a * tv, tv, H);
        ((float*)sW)[i]  = bw[gi] / gamma[d];
    }
    // CP half2 pack: 256 pairs, one per thread
    {
        int p = tid;                            // pair index < OT*DIM/2
        int gi = o0 * DIM + 2 * p;
        float cp0 = -0.7292730f * ww[gi];
        float cp1 = -0.7292730f * ww[gi + 1];
        ((u32*)sCPh)[p] = pack2(cp0, cp1);
    }
    __syncthreads();

    // ---- K1, K2 per o: warp w (w < OT) reduces o=w ----
    {
        int w = tid >> 5, lane = tid & 31;
        if (w < OT) {
            float4 wp = sW[w][lane];
            float4 g4 = ((const float4*)gamma)[lane];
            float4 b4 = ((const float4*)beta)[lane];
            float k1 = (wp.x * b4.x + wp.y * b4.y) + (wp.z * b4.z + wp.w * b4.w);
            float k2 = (wp.x * g4.x + wp.y * g4.y) + (wp.z * g4.z + wp.w * g4.w);
            #pragma unroll
            for (int off = 16; off; off >>= 1) {
                k1 += __shfl_xor_sync(~0u, k1, off);
                k2 += __shfl_xor_sync(~0u, k2, off);
            }
            if (lane == 0) { sK1[w] = k1; sK2[w] = k2; }
        }
    }
    __syncthreads();

    const int n0 = blockIdx.x * (THREADS * TOKPT) + tid;
    const float* xT = g_xnT + n0;

    float2 accw[OT][TOKPT], accb[OT][TOKPT];
    u32 acch[OT][TOKPT];
    #pragma unroll
    for (int o = 0; o < OT; o++)
        #pragma unroll
        for (int t = 0; t < TOKPT; t++) {
            accw[o][t] = make_float2(0.0f, 0.0f);
            accb[o][t] = make_float2(0.0f, 0.0f);
            acch[o][t] = 0u;
        }

    for (int dcb = 0; dcb < 8; dcb++) {
        #pragma unroll
        for (int dci = 0; dci < 4; dci++) {
            const int dc = dcb * 4 + dci;
            const float* p = xT + (size_t)(4 * dc) * NTOK;
            float2 xp[TOKPT][2], xq[TOKPT][2];
            #pragma unroll
            for (int t = 0; t < TOKPT; t++) {
                const float* pt = p + t * THREADS;
                xp[t][0] = make_float2(pt[0],        pt[NTOK]);
                xp[t][1] = make_float2(pt[2 * NTOK], pt[3 * NTOK]);
                xq[t][0] = fmul2(xp[t][0], xp[t][0]);
                xq[t][1] = fmul2(xp[t][1], xp[t][1]);
            }
            #pragma unroll
            for (int o = 0; o < OT; o++) {
                float4 A4 = sA [o][dc];
                float4 B4 = sB [o][dc];
                float4 M4 = sCM[o][dc];
                float4 W4 = sW [o][dc];
                uint2  C2 = sCPh[o][dc];
                float2 Al = make_float2(A4.x, A4.y), Ah = make_float2(A4.z, A4.w);
                float2 Bl = make_float2(B4.x, B4.y), Bh = make_float2(B4.z, B4.w);
                float2 Ml = make_float2(M4.x, M4.y), Mh = make_float2(M4.z, M4.w);
                float2 Wl = make_float2(W4.x, W4.y), Wh = make_float2(W4.z, W4.w);
                #pragma unroll
                for (int t = 0; t < TOKPT; t++) {
                    float2 m0 = ffma2(xq[t][0], Al, ffma2(xp[t][0], Bl, Ml));
                    float2 m1 = ffma2(xq[t][1], Ah, ffma2(xp[t][1], Bh, Mh));
                    u32 mh0 = pack2(m0.x, m0.y);
                    u32 mh1 = pack2(m1.x, m1.y);
                    u32 e0 = ex2h2(mh0);
                    u32 e1 = ex2h2(mh1);
                    u32 g0 = hmul2(mh0, e0);
                    u32 g1 = hmul2(mh1, e1);
                    acch[o][t] = hfma2(g0, C2.x, acch[o][t]);
                    acch[o][t] = hfma2(g1, C2.y, acch[o][t]);
                    accb[o][t] = ffma2(xp[t][0], Wl, accb[o][t]);
                    accb[o][t] = ffma2(xp[t][1], Wh, accb[o][t]);
                }
            }
        }
        // flush h2 partials into f32 accumulators (keeps fp16 sums short)
        #pragma unroll
        for (int o = 0; o < OT; o++)
            #pragma unroll
            for (int t = 0; t < TOKPT; t++) {
                __half2 hv = *reinterpret_cast<__half2*>(&acch[o][t]);
                float2 fv = __half22float2(hv);
                accw[o][t] = ffma2(fv, make_float2(1.0f, 1.0f), accw[o][t]);
                acch[o][t] = 0u;
            }
    }

    // ---- epilogue ----
    #pragma unroll
    for (int t = 0; t < TOKPT; t++) {
        int n = n0 + t * THREADS;
        float2 ms = g_musv[n];
        float* op = out + (size_t)n * ODIM + o0;
        float4 res;
        float* rp = (float*)&res;
        #pragma unroll
        for (int j = 0; j < 4; j++) {
            float ac = accb[j][t].x + accb[j][t].y;
            float b = fmaf(ms.y, ac - sK1[j], ms.x * sK2[j]);
            float e = ex2f(-1.44269504f * b);
            float sig = __frcp_rn(1.0f + e);
            rp[j] = fmaf(b, sig, accw[j][t].x + accw[j][t].y);
        }
        ((float4*)op)[0] = res;
    }
}

extern "C" void kernel_launch(void* const* d_in, const int* in_sizes, int n_in,
                              void* d_out, int out_size) {
    const float* x     = (const float*)d_in[0];
    const float* scale = (const float*)d_in[1];
    const float* trans = (const float*)d_in[2];
    const float* ww    = (const float*)d_in[3];
    const float* bw    = (const float*)d_in[4];
    const float* gamma = (const float*)d_in[5];
    const float* beta  = (const float*)d_in[6];
    float* out = (float*)d_out;

    ln_kernel<<<NTOK / 8, 256>>>(x, gamma, beta);
    dim3 grid(NTOK / (THREADS * TOKPT), ODIM / OT);
    wave_kernel<<<grid, THREADS>>>(scale, trans, ww, bw, gamma, beta, out);
}